// round 1
// baseline (speedup 1.0000x reference)
#include <cuda_runtime.h>
#include <cuda_bf16.h>
#include <cstdint>

// Problem constants
#define S_LEN   4096
#define H_DIM   4096
#define NQ_H    32
#define NKV_H   8
#define HD      128
#define QKV_N   6144                    // NQ*D + 2*NKV*D
#define SCALE_V 0.08838834764831845f    // 128^-0.5

// Scratch (device globals; no allocations allowed)
__device__ float g_qkv[(size_t)S_LEN * QKV_N];   // [S, 6144]: Q | K | V
__device__ float g_attn[(size_t)S_LEN * H_DIM];  // attention output [S, 4096]

// ---------------------------------------------------------------------------
// helpers
// ---------------------------------------------------------------------------
__device__ __forceinline__ unsigned f2tf(float x) {
    unsigned r;
    asm("cvt.rna.tf32.f32 %0, %1;" : "=r"(r) : "f"(x));
    return r;
}

__device__ __forceinline__ void mma_tf32(float c[4],
                                         unsigned a0, unsigned a1, unsigned a2, unsigned a3,
                                         unsigned b0, unsigned b1) {
    asm volatile(
        "mma.sync.aligned.m16n8k8.row.col.f32.tf32.tf32.f32 "
        "{%0,%1,%2,%3},{%4,%5,%6,%7},{%8,%9},{%0,%1,%2,%3};\n"
        : "+f"(c[0]), "+f"(c[1]), "+f"(c[2]), "+f"(c[3])
        : "r"(a0), "r"(a1), "r"(a2), "r"(a3), "r"(b0), "r"(b1));
}

// ---------------------------------------------------------------------------
// Generic TF32 GEMM: C[M,N] = A[M,K] @ B[K,N], all row-major fp32.
// BM=128, BN=128, BK=32, 256 threads (8 warps: 2 x 4 warp grid, 64x32 per warp)
// ---------------------------------------------------------------------------
#define GBM 128
#define GBN 128
#define GBK 32

__global__ __launch_bounds__(256, 1)
void gemm_tf32_kernel(const float* __restrict__ A, const float* __restrict__ B,
                      float* __restrict__ C, int M, int N, int K) {
    __shared__ unsigned As[GBM][GBK + 4];   // [128][36], stride 36 % 32 == 4
    __shared__ unsigned Bs[GBK][GBN + 4];   // [32][132], stride 132 % 32 == 4

    const int tid  = threadIdx.x;
    const int warp = tid >> 5;
    const int lane = tid & 31;
    const int g    = lane >> 2;   // groupID
    const int tg   = lane & 3;    // thread-in-group

    const int bm = blockIdx.y * GBM;
    const int bn = blockIdx.x * GBN;
    const int wm = (warp >> 2) * 64;   // warp row offset
    const int wn = (warp & 3) * 32;    // warp col offset

    float acc[4][4][4];
#pragma unroll
    for (int i = 0; i < 4; i++)
#pragma unroll
        for (int j = 0; j < 4; j++)
#pragma unroll
            for (int e = 0; e < 4; e++) acc[i][j][e] = 0.f;

    for (int kb = 0; kb < K; kb += GBK) {
        // load A tile: 128x32 fp32 -> tf32
#pragma unroll
        for (int i = 0; i < 4; i++) {
            int idx = tid + 256 * i;          // float4 index, 0..1023
            int r = idx >> 3;                 // 0..127
            int c = (idx & 7) << 2;           // 0..28
            float4 v = *(const float4*)(A + (size_t)(bm + r) * K + kb + c);
            As[r][c]     = f2tf(v.x);
            As[r][c + 1] = f2tf(v.y);
            As[r][c + 2] = f2tf(v.z);
            As[r][c + 3] = f2tf(v.w);
        }
        // load B tile: 32x128
#pragma unroll
        for (int i = 0; i < 4; i++) {
            int idx = tid + 256 * i;          // 0..1023
            int r = idx >> 5;                 // 0..31
            int c = (idx & 31) << 2;          // 0..124
            float4 v = *(const float4*)(B + (size_t)(kb + r) * N + bn + c);
            Bs[r][c]     = f2tf(v.x);
            Bs[r][c + 1] = f2tf(v.y);
            Bs[r][c + 2] = f2tf(v.z);
            Bs[r][c + 3] = f2tf(v.w);
        }
        __syncthreads();

#pragma unroll
        for (int ks = 0; ks < 4; ks++) {
            const int kk = ks << 3;
            unsigned a[4][4], b[4][2];
#pragma unroll
            for (int mt = 0; mt < 4; mt++) {
                int m0 = wm + mt * 16;
                a[mt][0] = As[m0 + g][kk + tg];
                a[mt][1] = As[m0 + g + 8][kk + tg];
                a[mt][2] = As[m0 + g][kk + tg + 4];
                a[mt][3] = As[m0 + g + 8][kk + tg + 4];
            }
#pragma unroll
            for (int nt = 0; nt < 4; nt++) {
                int n0 = wn + nt * 8;
                b[nt][0] = Bs[kk + tg][n0 + g];
                b[nt][1] = Bs[kk + tg + 4][n0 + g];
            }
#pragma unroll
            for (int mt = 0; mt < 4; mt++)
#pragma unroll
                for (int nt = 0; nt < 4; nt++)
                    mma_tf32(acc[mt][nt], a[mt][0], a[mt][1], a[mt][2], a[mt][3],
                             b[nt][0], b[nt][1]);
        }
        __syncthreads();
    }

    // epilogue
#pragma unroll
    for (int mt = 0; mt < 4; mt++) {
#pragma unroll
        for (int nt = 0; nt < 4; nt++) {
            int row0 = bm + wm + mt * 16 + g;
            int col  = bn + wn + nt * 8 + 2 * tg;
            C[(size_t)row0 * N + col]           = acc[mt][nt][0];
            C[(size_t)row0 * N + col + 1]       = acc[mt][nt][1];
            C[(size_t)(row0 + 8) * N + col]     = acc[mt][nt][2];
            C[(size_t)(row0 + 8) * N + col + 1] = acc[mt][nt][3];
        }
    }
}

// ---------------------------------------------------------------------------
// RoPE: applied in place to Q (heads 0..31) and K (heads 32..39) of g_qkv.
// Head h occupies cols [h*128, h*128+128) for h in 0..39.
// ---------------------------------------------------------------------------
__global__ void rope_kernel(const int* __restrict__ positions) {
    int idx = blockIdx.x * blockDim.x + threadIdx.x;
    const int total = S_LEN * 40 * 64;
    if (idx >= total) return;
    int d = idx & 63;
    int h = (idx >> 6) % 40;
    int s = idx / (40 * 64);

    float pos = (float)positions[s];
    // inv_freq = 10000^{-d/64}
    float inv = expf(-(float)d * (9.210340371976184f / 64.f));
    float f = pos * inv;
    float sn, cs;
    sincosf(f, &sn, &cs);

    size_t base = (size_t)s * QKV_N + h * 128;
    float x1 = g_qkv[base + d];
    float x2 = g_qkv[base + 64 + d];
    g_qkv[base + d]      = x1 * cs - x2 * sn;
    g_qkv[base + 64 + d] = x2 * cs + x1 * sn;
}

// ---------------------------------------------------------------------------
// Flash attention (causal, GQA 4:1). One CTA = one q-head x 128-query block.
// 256 threads = 8 warps; warp w owns query rows [16w, 16w+16).
// Key blocks of 64. Scores and PV both via tf32 mma; P staged through SMEM.
// ---------------------------------------------------------------------------
#define FA_QS_STRIDE 132   // 128 + 4
#define FA_PS_STRIDE 68    // 64 + 4
#define FA_SMEM ((128 * FA_QS_STRIDE + 64 * FA_QS_STRIDE + 64 * FA_QS_STRIDE + 128 * FA_PS_STRIDE) * 4)

__global__ __launch_bounds__(256, 1)
void flash_kernel() {
    extern __shared__ unsigned sh[];
    unsigned* Qs = sh;                               // [128][132]
    unsigned* Ks = Qs + 128 * FA_QS_STRIDE;          // [64][132]
    unsigned* Vs = Ks + 64 * FA_QS_STRIDE;           // [64][132]
    unsigned* Ps = Vs + 64 * FA_QS_STRIDE;           // [128][68]

    const int tid  = threadIdx.x;
    const int warp = tid >> 5;
    const int lane = tid & 31;
    const int g    = lane >> 2;
    const int tg   = lane & 3;

    const int qh  = blockIdx.x;                          // q head 0..31
    const int qb  = (int)gridDim.y - 1 - (int)blockIdx.y; // heavy blocks first
    const int kvh = qh >> 2;
    const int q0  = qb * 128;

    // load Q tile (128 x 128) with tf32 convert
    {
        const float* Qg = g_qkv + (size_t)q0 * QKV_N + qh * 128;
#pragma unroll
        for (int i = 0; i < 16; i++) {
            int idx = tid + 256 * i;           // 0..4095 (float4 units)
            int r = idx >> 5;                  // 0..127
            int c = (idx & 31) << 2;           // 0..124
            float4 v = *(const float4*)(Qg + (size_t)r * QKV_N + c);
            unsigned* dst = Qs + r * FA_QS_STRIDE + c;
            dst[0] = f2tf(v.x); dst[1] = f2tf(v.y);
            dst[2] = f2tf(v.z); dst[3] = f2tf(v.w);
        }
    }

    const int m0 = warp << 4;

    float oacc[16][4];
#pragma unroll
    for (int i = 0; i < 16; i++)
#pragma unroll
        for (int e = 0; e < 4; e++) oacc[i][e] = 0.f;
    float mrow[2] = {-1e30f, -1e30f};
    float lrow[2] = {0.f, 0.f};

    const float* Kg = g_qkv + 4096 + kvh * 128;   // K section col base
    const float* Vg = g_qkv + 5120 + kvh * 128;   // V section col base
    const int njb = 2 * qb + 2;

    for (int jb = 0; jb < njb; jb++) {
        const int k0g = jb * 64;
        __syncthreads();   // previous iteration done reading Ks/Vs/Ps
        // load K and V tiles (64 x 128 each)
#pragma unroll
        for (int i = 0; i < 8; i++) {
            int idx = tid + 256 * i;           // 0..2047
            int r = idx >> 5;                  // 0..63
            int c = (idx & 31) << 2;
            float4 kv = *(const float4*)(Kg + (size_t)(k0g + r) * QKV_N + c);
            unsigned* kd = Ks + r * FA_QS_STRIDE + c;
            kd[0] = f2tf(kv.x); kd[1] = f2tf(kv.y);
            kd[2] = f2tf(kv.z); kd[3] = f2tf(kv.w);
            float4 vv = *(const float4*)(Vg + (size_t)(k0g + r) * QKV_N + c);
            unsigned* vd = Vs + r * FA_QS_STRIDE + c;
            vd[0] = f2tf(vv.x); vd[1] = f2tf(vv.y);
            vd[2] = f2tf(vv.z); vd[3] = f2tf(vv.w);
        }
        __syncthreads();

        // scores: warp rows [m0, m0+16) x 64 keys
        float sacc[8][4];
#pragma unroll
        for (int nt = 0; nt < 8; nt++)
#pragma unroll
            for (int e = 0; e < 4; e++) sacc[nt][e] = 0.f;

#pragma unroll
        for (int ks = 0; ks < 16; ks++) {
            const int kk = ks << 3;
            unsigned a0 = Qs[(m0 + g) * FA_QS_STRIDE + kk + tg];
            unsigned a1 = Qs[(m0 + g + 8) * FA_QS_STRIDE + kk + tg];
            unsigned a2 = Qs[(m0 + g) * FA_QS_STRIDE + kk + tg + 4];
            unsigned a3 = Qs[(m0 + g + 8) * FA_QS_STRIDE + kk + tg + 4];
#pragma unroll
            for (int nt = 0; nt < 8; nt++) {
                unsigned b0 = Ks[(nt * 8 + g) * FA_QS_STRIDE + kk + tg];
                unsigned b1 = Ks[(nt * 8 + g) * FA_QS_STRIDE + kk + tg + 4];
                mma_tf32(sacc[nt], a0, a1, a2, a3, b0, b1);
            }
        }

        // online softmax update (2 rows per thread: g and g+8)
        const bool do_mask = (jb >= njb - 2);
        const int qrow0 = q0 + m0 + g;
        const int qrow1 = qrow0 + 8;
        float rmax[2] = {-1e30f, -1e30f};
#pragma unroll
        for (int nt = 0; nt < 8; nt++) {
#pragma unroll
            for (int e = 0; e < 4; e++) {
                int row = e >> 1;
                int key = k0g + nt * 8 + 2 * tg + (e & 1);
                float s = sacc[nt][e] * SCALE_V;
                if (do_mask && key > (row ? qrow1 : qrow0)) s = -1e30f;
                sacc[nt][e] = s;
                rmax[row] = fmaxf(rmax[row], s);
            }
        }
#pragma unroll
        for (int r = 0; r < 2; r++) {
            rmax[r] = fmaxf(rmax[r], __shfl_xor_sync(0xffffffffu, rmax[r], 1));
            rmax[r] = fmaxf(rmax[r], __shfl_xor_sync(0xffffffffu, rmax[r], 2));
        }
        float mnew[2], alpha[2], rsum[2] = {0.f, 0.f};
#pragma unroll
        for (int r = 0; r < 2; r++) {
            mnew[r]  = fmaxf(mrow[r], rmax[r]);
            alpha[r] = __expf(mrow[r] - mnew[r]);
            mrow[r]  = mnew[r];
        }
        // p = exp(s - m_new), write tf32 P tile to shared
#pragma unroll
        for (int nt = 0; nt < 8; nt++) {
#pragma unroll
            for (int e = 0; e < 4; e++) {
                int row = e >> 1;
                float p = __expf(sacc[nt][e] - mnew[row]);
                rsum[row] += p;
                Ps[(m0 + g + (row ? 8 : 0)) * FA_PS_STRIDE + nt * 8 + 2 * tg + (e & 1)] = f2tf(p);
            }
        }
#pragma unroll
        for (int r = 0; r < 2; r++) {
            rsum[r] += __shfl_xor_sync(0xffffffffu, rsum[r], 1);
            rsum[r] += __shfl_xor_sync(0xffffffffu, rsum[r], 2);
            lrow[r] = lrow[r] * alpha[r] + rsum[r];
        }
        // rescale O accumulator
#pragma unroll
        for (int nt = 0; nt < 16; nt++) {
            oacc[nt][0] *= alpha[0];
            oacc[nt][1] *= alpha[0];
            oacc[nt][2] *= alpha[1];
            oacc[nt][3] *= alpha[1];
        }
        __syncthreads();   // P visible to all warps (each warp uses only its own rows,
                           // but keep full-tile coherence cheap & safe)

        // PV: O[16 x 128] += P[16 x 64] @ V[64 x 128]
#pragma unroll
        for (int ks = 0; ks < 8; ks++) {
            const int kk = ks << 3;
            unsigned a0 = Ps[(m0 + g) * FA_PS_STRIDE + kk + tg];
            unsigned a1 = Ps[(m0 + g + 8) * FA_PS_STRIDE + kk + tg];
            unsigned a2 = Ps[(m0 + g) * FA_PS_STRIDE + kk + tg + 4];
            unsigned a3 = Ps[(m0 + g + 8) * FA_PS_STRIDE + kk + tg + 4];
#pragma unroll
            for (int nt = 0; nt < 16; nt++) {
                unsigned b0 = Vs[(kk + tg) * FA_QS_STRIDE + nt * 8 + g];
                unsigned b1 = Vs[(kk + tg + 4) * FA_QS_STRIDE + nt * 8 + g];
                mma_tf32(oacc[nt], a0, a1, a2, a3, b0, b1);
            }
        }
    }

    // normalize and write out: attn[s, qh*128 + d]
    float inv0 = 1.f / lrow[0];
    float inv1 = 1.f / lrow[1];
    float* out0 = g_attn + (size_t)(q0 + m0 + g) * H_DIM + qh * 128;
    float* out1 = g_attn + (size_t)(q0 + m0 + g + 8) * H_DIM + qh * 128;
#pragma unroll
    for (int nt = 0; nt < 16; nt++) {
        int col = nt * 8 + 2 * tg;
        out0[col]     = oacc[nt][0] * inv0;
        out0[col + 1] = oacc[nt][1] * inv0;
        out1[col]     = oacc[nt][2] * inv1;
        out1[col + 1] = oacc[nt][3] * inv1;
    }
}

// ---------------------------------------------------------------------------
// launch
// ---------------------------------------------------------------------------
extern "C" void kernel_launch(void* const* d_in, const int* in_sizes, int n_in,
                              void* d_out, int out_size) {
    const int*   positions = (const int*)d_in[0];
    const float* hidden    = (const float*)d_in[1];
    const float* w_qkv     = (const float*)d_in[2];
    const float* w_o       = (const float*)d_in[3];
    float*       out       = (float*)d_out;

    float* qkv_ptr  = nullptr;
    float* attn_ptr = nullptr;
    cudaGetSymbolAddress((void**)&qkv_ptr, g_qkv);
    cudaGetSymbolAddress((void**)&attn_ptr, g_attn);

    cudaFuncSetAttribute(flash_kernel, cudaFuncAttributeMaxDynamicSharedMemorySize, FA_SMEM);

    // 1) QKV projection: [4096,4096] @ [4096,6144]
    gemm_tf32_kernel<<<dim3(QKV_N / GBN, S_LEN / GBM), 256>>>(
        hidden, w_qkv, qkv_ptr, S_LEN, QKV_N, H_DIM);

    // 2) RoPE on Q and K in place
    rope_kernel<<<(S_LEN * 40 * 64 + 255) / 256, 256>>>(positions);

    // 3) causal GQA flash attention -> g_attn
    flash_kernel<<<dim3(NQ_H, S_LEN / 128), 256, FA_SMEM>>>();

    // 4) output projection: [4096,4096] @ [4096,4096] -> d_out
    gemm_tf32_kernel<<<dim3(H_DIM / GBN, S_LEN / GBM), 256>>>(
        attn_ptr, w_o, out, S_LEN, H_DIM, H_DIM);
}

// round 16
// speedup vs baseline: 1.6706x; 1.6706x over previous
#include <cuda_runtime.h>
#include <cstdint>

// ---------------------------------------------------------------------------
// Problem constants
// ---------------------------------------------------------------------------
#define S_LEN   4096
#define H_DIM   4096
#define NQ_H    32
#define NKV_H   8
#define QKV_N   6144
#define SCALE_V 0.08838834764831845f    // 128^-0.5

// ---------------------------------------------------------------------------
// Device scratch (static globals; no allocation allowed)
// ---------------------------------------------------------------------------
__device__ float g_hid  [(size_t)S_LEN * H_DIM];   // tf32-rounded hidden
__device__ float g_qkv  [(size_t)S_LEN * QKV_N];   // rounded Q|K|V
__device__ float g_vt   [(size_t)8 * 128 * S_LEN]; // V transposed [kvh*128+d][s]
__device__ float g_attn [(size_t)S_LEN * H_DIM];   // rounded attention out
__device__ float g_wqkvT[(size_t)QKV_N * H_DIM];   // w_qkv^T [N][K], rounded
__device__ float g_woT  [(size_t)H_DIM * H_DIM];   // w_o^T   [N][K], rounded

// ---------------------------------------------------------------------------
// helpers
// ---------------------------------------------------------------------------
__device__ __forceinline__ float tf32r(float x) {
    unsigned u;
    asm("cvt.rna.tf32.f32 %0, %1;" : "=r"(u) : "f"(x));
    return __uint_as_float(u);
}

__device__ __forceinline__ void mma_tf32(float c[4],
                                         unsigned a0, unsigned a1, unsigned a2, unsigned a3,
                                         unsigned b0, unsigned b1) {
    asm volatile(
        "mma.sync.aligned.m16n8k8.row.col.f32.tf32.tf32.f32 "
        "{%0,%1,%2,%3},{%4,%5,%6,%7},{%8,%9},{%0,%1,%2,%3};\n"
        : "+f"(c[0]), "+f"(c[1]), "+f"(c[2]), "+f"(c[3])
        : "r"(a0), "r"(a1), "r"(a2), "r"(a3), "r"(b0), "r"(b1));
}

__device__ __forceinline__ void cp16(unsigned dst, const float* src) {
    asm volatile("cp.async.cg.shared.global [%0], [%1], 16;\n" :: "r"(dst), "l"(src));
}
__device__ __forceinline__ void cp_commit() {
    asm volatile("cp.async.commit_group;\n" ::);
}
template <int N> __device__ __forceinline__ void cp_wait() {
    asm volatile("cp.async.wait_group %0;\n" :: "n"(N));
}

__device__ __forceinline__ void ldsm4(unsigned& r0, unsigned& r1, unsigned& r2, unsigned& r3,
                                      unsigned addr) {
    asm volatile("ldmatrix.sync.aligned.m8n8.x4.shared.b16 {%0,%1,%2,%3}, [%4];\n"
                 : "=r"(r0), "=r"(r1), "=r"(r2), "=r"(r3) : "r"(addr));
}

// ---------------------------------------------------------------------------
// prep kernels
// ---------------------------------------------------------------------------
__global__ void round_copy_kernel(const float* __restrict__ in, float* __restrict__ out, int n4) {
    int i = blockIdx.x * blockDim.x + threadIdx.x;
    if (i >= n4) return;
    float4 v = ((const float4*)in)[i];
    v.x = tf32r(v.x); v.y = tf32r(v.y); v.z = tf32r(v.z); v.w = tf32r(v.w);
    ((float4*)out)[i] = v;
}

// out[c][r] = round(in[r][c]);   in: [R][C]
__global__ void transpose_round_kernel(const float* __restrict__ in, float* __restrict__ out,
                                       int R, int C) {
    __shared__ float t[32][33];
    int c0 = blockIdx.x * 32, r0 = blockIdx.y * 32;
    int tx = threadIdx.x, ty = threadIdx.y;
#pragma unroll
    for (int i = 0; i < 32; i += 8)
        t[ty + i][tx] = tf32r(in[(size_t)(r0 + ty + i) * C + c0 + tx]);
    __syncthreads();
#pragma unroll
    for (int i = 0; i < 32; i += 8)
        out[(size_t)(c0 + ty + i) * R + r0 + tx] = t[tx][ty + i];
}

// V section of g_qkv -> g_vt[(kvh*128+d)][s]
__global__ void vtrans_kernel() {
    __shared__ float t[32][33];
    int c0 = blockIdx.x * 32;   // v-col 0..1023
    int r0 = blockIdx.y * 32;   // s
    int tx = threadIdx.x, ty = threadIdx.y;
#pragma unroll
    for (int i = 0; i < 32; i += 8)
        t[ty + i][tx] = g_qkv[(size_t)(r0 + ty + i) * QKV_N + 5120 + c0 + tx];
    __syncthreads();
#pragma unroll
    for (int i = 0; i < 32; i += 8)
        g_vt[(size_t)(c0 + ty + i) * S_LEN + r0 + tx] = t[tx][ty + i];
}

// RoPE in place on Q (heads 0..31) + K (heads 32..39), rounded on write.
__global__ void rope_kernel(const int* __restrict__ positions) {
    int idx = blockIdx.x * blockDim.x + threadIdx.x;
    const int total = S_LEN * 40 * 64;
    if (idx >= total) return;
    int d = idx & 63;
    int h = (idx >> 6) % 40;
    int s = idx / (40 * 64);

    float pos = (float)positions[s];
    float inv = expf(-(float)d * (9.210340371976184f / 64.f));
    float f = pos * inv, sn, cs;
    sincosf(f, &sn, &cs);

    size_t base = (size_t)s * QKV_N + h * 128;
    float x1 = g_qkv[base + d];
    float x2 = g_qkv[base + 64 + d];
    g_qkv[base + d]      = tf32r(x1 * cs - x2 * sn);
    g_qkv[base + 64 + d] = tf32r(x2 * cs + x1 * sn);
}

// ---------------------------------------------------------------------------
// NT GEMM: C[M,N] = A[M,K] @ Bt[N,K]^T. Inputs pre-rounded to tf32.
// BM=128 BN=128 BK=32, 256 threads, cp.async double buffer, ldmatrix frags.
// SMEM (dynamic): 2 stages x (A 1024 + B 1024) 16B units = 64KB.
// __launch_bounds__(256, 2): cap regs at 128 -> 2 CTAs/SM (128KB smem < 228KB)
// for latency hiding (R0 baseline showed occ=12.5%, issue=19.7%).
// ---------------------------------------------------------------------------
template <bool ROUND>
__global__ __launch_bounds__(256, 2)
void gemm_nt_kernel(const float* __restrict__ A, const float* __restrict__ Bt,
                    float* __restrict__ C, int M, int N, int K) {
    extern __shared__ __align__(16) float smem[];
    unsigned sb = (unsigned)__cvta_generic_to_shared(smem);

    const int tid = threadIdx.x, lane = tid & 31, warp = tid >> 5;
    const int bm = blockIdx.y * 128, bn = blockIdx.x * 128;
    const int wm = (warp >> 2) * 64, wn = (warp & 3) * 32;
    const int urow = lane & 15, usel = lane >> 4, xr = lane & 7;
    const int g = lane >> 2, tg = lane & 3;

    float acc[4][4][4];
#pragma unroll
    for (int i = 0; i < 4; i++)
#pragma unroll
        for (int j = 0; j < 4; j++)
#pragma unroll
            for (int e = 0; e < 4; e++) acc[i][j][e] = 0.f;

    const float* Abase = A + (size_t)bm * K;
    const float* Bbase = Bt + (size_t)bn * K;

    auto load_stage = [&](int kb, int s) {
#pragma unroll
        for (int i = 0; i < 4; i++) {
            int uid = tid + 256 * i;
            int m = uid >> 3, u = uid & 7;
            cp16(sb + ((s * 2048 + m * 8 + (u ^ (m & 7))) << 4),
                 Abase + (size_t)m * K + kb + u * 4);
        }
#pragma unroll
        for (int i = 0; i < 4; i++) {
            int uid = tid + 256 * i;
            int n = uid >> 3, u = uid & 7;
            cp16(sb + ((s * 2048 + 1024 + n * 8 + (u ^ (n & 7))) << 4),
                 Bbase + (size_t)n * K + kb + u * 4);
        }
    };

    load_stage(0, 0);
    cp_commit();

    const int nkt = K >> 5;
    for (int kt = 0; kt < nkt; kt++) {
        if (kt + 1 < nkt) load_stage((kt + 1) << 5, (kt + 1) & 1);
        cp_commit();
        cp_wait<1>();
        __syncthreads();

        unsigned base = sb + (((kt & 1) * 2048) << 4);
#pragma unroll
        for (int ks = 0; ks < 4; ks++) {
            unsigned ua = (unsigned)((2 * ks + usel) ^ xr);
            unsigned a[4][4], b[2][4];
#pragma unroll
            for (int mt = 0; mt < 4; mt++)
                ldsm4(a[mt][0], a[mt][1], a[mt][2], a[mt][3],
                      base + (((wm + mt * 16 + urow) * 8 + ua) << 4));
#pragma unroll
            for (int p = 0; p < 2; p++)
                ldsm4(b[p][0], b[p][1], b[p][2], b[p][3],
                      base + ((1024 + (wn + p * 16 + urow) * 8 + ua) << 4));
#pragma unroll
            for (int mt = 0; mt < 4; mt++)
#pragma unroll
                for (int nt = 0; nt < 4; nt++)
                    mma_tf32(acc[mt][nt], a[mt][0], a[mt][1], a[mt][2], a[mt][3],
                             b[nt >> 1][nt & 1], b[nt >> 1][2 + (nt & 1)]);
        }
        __syncthreads();
    }

    // epilogue
#pragma unroll
    for (int mt = 0; mt < 4; mt++) {
#pragma unroll
        for (int nt = 0; nt < 4; nt++) {
            int r0 = bm + wm + mt * 16 + g;
            int c  = bn + wn + nt * 8 + 2 * tg;
            float2 v0, v1;
            if (ROUND) {
                v0 = make_float2(tf32r(acc[mt][nt][0]), tf32r(acc[mt][nt][1]));
                v1 = make_float2(tf32r(acc[mt][nt][2]), tf32r(acc[mt][nt][3]));
            } else {
                v0 = make_float2(acc[mt][nt][0], acc[mt][nt][1]);
                v1 = make_float2(acc[mt][nt][2], acc[mt][nt][3]);
            }
            *(float2*)(C + (size_t)r0 * N + c)       = v0;
            *(float2*)(C + (size_t)(r0 + 8) * N + c) = v1;
        }
    }
}

// ---------------------------------------------------------------------------
// Flash attention (causal, GQA 4:1). CTA = 1 q-head x 128-query block, 8 warps.
// SMEM 16B-unit map: Q [0,4096) | K 4096+s*2048 | Vt 8192+s*2048 | P 12288..14336
// Total 14336 units = 229376 B dynamic.
// ---------------------------------------------------------------------------
#define FA_SMEM_BYTES (14336 * 16)

__global__ __launch_bounds__(256, 1)
void flash_kernel() {
    extern __shared__ __align__(16) float sm[];
    unsigned sb = (unsigned)__cvta_generic_to_shared(sm);

    const int tid = threadIdx.x, lane = tid & 31, warp = tid >> 5;
    const int g = lane >> 2, tg = lane & 3;
    const int urow = lane & 15, usel = lane >> 4, xr = lane & 7;

    const int qh  = blockIdx.x;
    const int qb  = (int)gridDim.y - 1 - (int)blockIdx.y;  // heavy first
    const int kvh = qh >> 2;
    const int q0  = qb * 128;
    const int m0  = warp * 16;

    const float* Qg = g_qkv + (size_t)q0 * QKV_N + qh * 128;
    const float* Kg = g_qkv + 4096 + kvh * 128;
    const float* Vg = g_vt + (size_t)(kvh * 128) * S_LEN;

    // Q load (128 rows x 32 units)
#pragma unroll
    for (int i = 0; i < 16; i++) {
        int uid = tid + 256 * i;
        int m = uid >> 5, u = uid & 31;
        cp16(sb + ((m * 32 + (u ^ (m & 7))) << 4), Qg + (size_t)m * QKV_N + u * 4);
    }

    auto load_kv = [&](int jb) {
        int s = jb & 1, k0 = jb * 64;
#pragma unroll
        for (int i = 0; i < 8; i++) {
            int uid = tid + 256 * i;
            int r = uid >> 5, u = uid & 31;
            cp16(sb + ((4096 + s * 2048 + r * 32 + (u ^ (r & 7))) << 4),
                 Kg + (size_t)(k0 + r) * QKV_N + u * 4);
        }
#pragma unroll
        for (int i = 0; i < 8; i++) {
            int uid = tid + 256 * i;
            int d = uid >> 4, u = uid & 15;
            cp16(sb + ((8192 + s * 2048 + d * 16 + (u ^ (d & 7))) << 4),
                 Vg + (size_t)d * S_LEN + k0 + u * 4);
        }
    };

    load_kv(0);
    cp_commit();

    float oacc[16][4];
#pragma unroll
    for (int i = 0; i < 16; i++)
#pragma unroll
        for (int e = 0; e < 4; e++) oacc[i][e] = 0.f;
    float mrow[2] = {-1e30f, -1e30f};
    float lrow[2] = {0.f, 0.f};

    const int njb = 2 * qb + 2;
    for (int jb = 0; jb < njb; jb++) {
        if (jb + 1 < njb) load_kv(jb + 1);
        cp_commit();
        cp_wait<1>();
        __syncthreads();

        const int s = jb & 1;
        const int k0g = jb * 64;

        // ---- scores: S[16 x 64] = Q_warp @ K^T ----
        float sacc[8][4];
#pragma unroll
        for (int nt = 0; nt < 8; nt++)
#pragma unroll
            for (int e = 0; e < 4; e++) sacc[nt][e] = 0.f;

#pragma unroll
        for (int ks = 0; ks < 16; ks++) {
            unsigned ua = (unsigned)((2 * ks + usel) ^ xr);
            unsigned a[4], b[4][4];
            ldsm4(a[0], a[1], a[2], a[3], sb + (((m0 + urow) * 32 + ua) << 4));
#pragma unroll
            for (int p = 0; p < 4; p++)
                ldsm4(b[p][0], b[p][1], b[p][2], b[p][3],
                      sb + ((4096 + s * 2048 + (p * 16 + urow) * 32 + ua) << 4));
#pragma unroll
            for (int nt = 0; nt < 8; nt++)
                mma_tf32(sacc[nt], a[0], a[1], a[2], a[3],
                         b[nt >> 1][nt & 1], b[nt >> 1][2 + (nt & 1)]);
        }

        // ---- online softmax ----
        const bool do_mask = (jb >= njb - 2);
        const int qrow0 = q0 + m0 + g;
        const int qrow1 = qrow0 + 8;
        float rmax[2] = {-1e30f, -1e30f};
#pragma unroll
        for (int nt = 0; nt < 8; nt++) {
#pragma unroll
            for (int e = 0; e < 4; e++) {
                int row = e >> 1;
                int key = k0g + nt * 8 + 2 * tg + (e & 1);
                float v = sacc[nt][e] * SCALE_V;
                if (do_mask && key > (row ? qrow1 : qrow0)) v = -1e30f;
                sacc[nt][e] = v;
                rmax[row] = fmaxf(rmax[row], v);
            }
        }
#pragma unroll
        for (int r = 0; r < 2; r++) {
            rmax[r] = fmaxf(rmax[r], __shfl_xor_sync(0xffffffffu, rmax[r], 1));
            rmax[r] = fmaxf(rmax[r], __shfl_xor_sync(0xffffffffu, rmax[r], 2));
        }
        float mnew[2], alpha[2], rsum[2] = {0.f, 0.f};
#pragma unroll
        for (int r = 0; r < 2; r++) {
            mnew[r]  = fmaxf(mrow[r], rmax[r]);
            alpha[r] = __expf(mrow[r] - mnew[r]);
            mrow[r]  = mnew[r];
        }

        // P = exp(s - m_new), rounded, into swizzled SMEM (own warp rows only)
        float* Pf = sm + 12288 * 4;
#pragma unroll
        for (int nt = 0; nt < 8; nt++) {
            float p0 = __expf(sacc[nt][0] - mnew[0]);
            float p1 = __expf(sacc[nt][1] - mnew[0]);
            float p2 = __expf(sacc[nt][2] - mnew[1]);
            float p3 = __expf(sacc[nt][3] - mnew[1]);
            rsum[0] += p0 + p1;
            rsum[1] += p2 + p3;
            int w  = nt * 8 + 2 * tg;
            int u0 = (w >> 2) ^ (g & 7);        // rows g and g+8 share (row&7)
            int r0 = m0 + g, r1 = r0 + 8;
            *(float2*)(Pf + r0 * 64 + u0 * 4 + (w & 3)) = make_float2(tf32r(p0), tf32r(p1));
            *(float2*)(Pf + r1 * 64 + u0 * 4 + (w & 3)) = make_float2(tf32r(p2), tf32r(p3));
        }
#pragma unroll
        for (int r = 0; r < 2; r++) {
            rsum[r] += __shfl_xor_sync(0xffffffffu, rsum[r], 1);
            rsum[r] += __shfl_xor_sync(0xffffffffu, rsum[r], 2);
            lrow[r] = lrow[r] * alpha[r] + rsum[r];
        }
#pragma unroll
        for (int nt = 0; nt < 16; nt++) {
            oacc[nt][0] *= alpha[0];
            oacc[nt][1] *= alpha[0];
            oacc[nt][2] *= alpha[1];
            oacc[nt][3] *= alpha[1];
        }
        __syncwarp();

        // ---- PV: O[16 x 128] += P[16 x 64] @ V[64 x 128] ----
#pragma unroll
        for (int ks = 0; ks < 8; ks++) {
            unsigned ua = (unsigned)((2 * ks + usel) ^ xr);
            unsigned a[4], b[8][4];
            ldsm4(a[0], a[1], a[2], a[3],
                  sb + ((12288 + (m0 + urow) * 16 + ua) << 4));
#pragma unroll
            for (int p = 0; p < 8; p++)
                ldsm4(b[p][0], b[p][1], b[p][2], b[p][3],
                      sb + ((8192 + s * 2048 + (p * 16 + urow) * 16 + ua) << 4));
#pragma unroll
            for (int nt = 0; nt < 16; nt++)
                mma_tf32(oacc[nt], a[0], a[1], a[2], a[3],
                         b[nt >> 1][nt & 1], b[nt >> 1][2 + (nt & 1)]);
        }
        __syncthreads();
    }

    // output (rounded: feeds GEMM2)
    float inv0 = 1.f / lrow[0];
    float inv1 = 1.f / lrow[1];
    float* out0 = g_attn + (size_t)(q0 + m0 + g) * H_DIM + qh * 128;
    float* out1 = g_attn + (size_t)(q0 + m0 + g + 8) * H_DIM + qh * 128;
#pragma unroll
    for (int nt = 0; nt < 16; nt++) {
        int col = nt * 8 + 2 * tg;
        *(float2*)(out0 + col) = make_float2(tf32r(oacc[nt][0] * inv0), tf32r(oacc[nt][1] * inv0));
        *(float2*)(out1 + col) = make_float2(tf32r(oacc[nt][2] * inv1), tf32r(oacc[nt][3] * inv1));
    }
}

// ---------------------------------------------------------------------------
// launch
// ---------------------------------------------------------------------------
extern "C" void kernel_launch(void* const* d_in, const int* in_sizes, int n_in,
                              void* d_out, int out_size) {
    const int*   positions = (const int*)d_in[0];
    const float* hidden    = (const float*)d_in[1];
    const float* w_qkv     = (const float*)d_in[2];
    const float* w_o       = (const float*)d_in[3];
    float*       out       = (float*)d_out;

    float *hid_p, *qkv_p, *attn_p, *wqkvT_p, *woT_p;
    cudaGetSymbolAddress((void**)&hid_p, g_hid);
    cudaGetSymbolAddress((void**)&qkv_p, g_qkv);
    cudaGetSymbolAddress((void**)&attn_p, g_attn);
    cudaGetSymbolAddress((void**)&wqkvT_p, g_wqkvT);
    cudaGetSymbolAddress((void**)&woT_p, g_woT);

    cudaFuncSetAttribute(flash_kernel, cudaFuncAttributeMaxDynamicSharedMemorySize, FA_SMEM_BYTES);
    cudaFuncSetAttribute(gemm_nt_kernel<true>,  cudaFuncAttributeMaxDynamicSharedMemorySize, 65536);
    cudaFuncSetAttribute(gemm_nt_kernel<false>, cudaFuncAttributeMaxDynamicSharedMemorySize, 65536);

    // prep: round hidden, transpose+round weights
    round_copy_kernel<<<(S_LEN * H_DIM / 4 + 255) / 256, 256>>>(hidden, hid_p, S_LEN * H_DIM / 4);
    transpose_round_kernel<<<dim3(QKV_N / 32, H_DIM / 32), dim3(32, 8)>>>(w_qkv, wqkvT_p, H_DIM, QKV_N);
    transpose_round_kernel<<<dim3(H_DIM / 32, H_DIM / 32), dim3(32, 8)>>>(w_o, woT_p, H_DIM, H_DIM);

    // 1) QKV projection (rounded out)
    gemm_nt_kernel<true><<<dim3(QKV_N / 128, S_LEN / 128), 256, 65536>>>(
        hid_p, wqkvT_p, qkv_p, S_LEN, QKV_N, H_DIM);

    // 2) RoPE (rounded in place)
    rope_kernel<<<(S_LEN * 40 * 64 + 255) / 256, 256>>>(positions);

    // 3) V transpose -> g_vt
    vtrans_kernel<<<dim3(1024 / 32, S_LEN / 32), dim3(32, 8)>>>();

    // 4) flash attention -> g_attn (rounded)
    flash_kernel<<<dim3(NQ_H, S_LEN / 128), 256, FA_SMEM_BYTES>>>();

    // 5) output projection (raw fp32 out)
    gemm_nt_kernel<false><<<dim3(H_DIM / 128, S_LEN / 128), 256, 65536>>>(
        attn_p, woT_p, out, S_LEN, H_DIM, H_DIM);
}